// round 5
// baseline (speedup 1.0000x reference)
#include <cuda_runtime.h>
#include <cstdint>

#define T_TOK 8192
#define HID   2048
#define NEXP  8
#define INTER 2816
#define GUDIM (2*INTER)
#define MAX_MT 136
#define TILE 128
#define BK   32
#define LDA  36   // padded smem row stride (floats)

// ---------------- scratch (device globals: no allocations allowed) ----------------
__device__ int    g_topi[T_TOK*2];
__device__ float  g_topw[T_TOK*2];
__device__ int    g_tok [NEXP*T_TOK];
__device__ float  g_wt  [NEXP*T_TOK];
__device__ int    g_cnt [NEXP];
__device__ int    g_off [NEXP];
__device__ int    g_tileE[MAX_MT+8];
__device__ int    g_tileB[MAX_MT+8];
__device__ int    g_nTiles;
__device__ int    g_mmaOK;
__device__ __align__(16) float g_inter[(size_t)(16384+128)*INTER];   // ~186 MB

// ---------------- helpers ----------------
__device__ __forceinline__ uint32_t f2tf32(float f) {
    uint32_t u;
    asm volatile("cvt.rna.tf32.f32 %0, %1;\n" : "=r"(u) : "f"(f));
    return u;
}

__device__ __forceinline__ void mma_tf32(float* d, const uint32_t* a, const uint32_t* b) {
    asm volatile(
        "mma.sync.aligned.m16n8k8.row.col.f32.tf32.tf32.f32 "
        "{%0,%1,%2,%3}, {%4,%5,%6,%7}, {%8,%9}, {%0,%1,%2,%3};\n"
        : "+f"(d[0]), "+f"(d[1]), "+f"(d[2]), "+f"(d[3])
        : "r"(a[0]), "r"(a[1]), "r"(a[2]), "r"(a[3]), "r"(b[0]), "r"(b[1]));
}

#define CP_ASYNC_G(dst, src, sz) \
    asm volatile("cp.async.cg.shared.global [%0], [%1], 16, %2;\n" :: "r"(dst), "l"(src), "r"(sz))
#define CP_COMMIT() asm volatile("cp.async.commit_group;\n")
#define CP_WAIT(n)  asm volatile("cp.async.wait_group %0;\n" :: "n"(n))

// ---------------- 0) mma self-test: validates instruction + fragment layout ----------------
__global__ void mmatest_k() {
    __shared__ float As[16][8];  // [m][k]
    __shared__ float Bs[8][8];   // [n][k]
    int lane = threadIdx.x & 31;
    if (lane < 16)
        for (int k = 0; k < 8; k++) As[lane][k] = (float)((lane * 3 + k * 5) % 7 - 3);
    if (lane < 8)
        for (int k = 0; k < 8; k++) Bs[lane][k] = (float)((lane * 5 + k * 3) % 5 - 2);
    __syncwarp();
    int g = lane >> 2, t = lane & 3;
    uint32_t a[4], b[2];
    a[0] = f2tf32(As[g][t]);     a[1] = f2tf32(As[g + 8][t]);
    a[2] = f2tf32(As[g][t + 4]); a[3] = f2tf32(As[g + 8][t + 4]);
    b[0] = f2tf32(Bs[g][t]);     b[1] = f2tf32(Bs[g][t + 4]);
    float d[4] = {0.f, 0.f, 0.f, 0.f};
    mma_tf32(d, a, b);
    bool ok = true;
    int mr[2] = {g, g + 8}, nc[2] = {2 * t, 2 * t + 1};
    for (int i = 0; i < 2; i++)
        for (int j = 0; j < 2; j++) {
            float ref = 0.f;
            for (int k = 0; k < 8; k++) ref += As[mr[i]][k] * Bs[nc[j]][k];
            if (d[i * 2 + j] != ref) ok = false;   // integer data: exact
        }
    unsigned m = __ballot_sync(0xffffffffu, ok);
    if (lane == 0) g_mmaOK = (m == 0xffffffffu) ? 1 : 0;
}

// ---------------- 1) router (fp64 accum; biases applied post-softmax, exact since gate_b==0) ----
__global__ void router_k(const float* __restrict__ x, const float* __restrict__ gw,
                         const float* __restrict__ b1, const float* __restrict__ b2) {
    int lane = threadIdx.x & 31, wid = threadIdx.x >> 5;
    int t = blockIdx.x * 8 + wid;
    const float* xr = x + (size_t)t * HID;
    double acc[NEXP];
#pragma unroll
    for (int e = 0; e < NEXP; e++) acc[e] = 0.0;
    for (int i = lane; i < HID; i += 32) {
        float xv = xr[i];
#pragma unroll
        for (int e = 0; e < NEXP; e++)
            acc[e] += (double)xv * (double)gw[e * HID + i];
    }
#pragma unroll
    for (int e = 0; e < NEXP; e++) {
        double v = acc[e];
        for (int o = 16; o; o >>= 1) v += __shfl_down_sync(0xffffffffu, v, o);
        acc[e] = v;
    }
    if (lane == 0) {
        float l[NEXP], m = -1e30f;
#pragma unroll
        for (int e = 0; e < NEXP; e++) { l[e] = (float)acc[e]; m = fmaxf(m, l[e]); }
        float s = 0.f, p[NEXP];
#pragma unroll
        for (int e = 0; e < NEXP; e++) { p[e] = expf(l[e] - m); s += p[e]; }
        float r[NEXP];
#pragma unroll
        for (int e = 0; e < NEXP; e++) r[e] = p[e] / s + b1[e] + b2[e];
        int c1 = 0;
#pragma unroll
        for (int e = 1; e < NEXP; e++) if (r[e] > r[c1]) c1 = e;
        int c2 = (c1 == 0) ? 1 : 0;
#pragma unroll
        for (int e = 0; e < NEXP; e++) if (e != c1 && r[e] > r[c2]) c2 = e;
        g_topi[2*t] = c1; g_topi[2*t+1] = c2;
        g_topw[2*t] = r[c1]; g_topw[2*t+1] = r[c2];
    }
}

// ---------------- 2) deterministic per-expert token lists ----------------
__global__ void lists_k() {
    int e = blockIdx.x, tid = threadIdx.x, lane = tid & 31, wid = tid >> 5;
    __shared__ int wcnt[8];
    __shared__ int basePos;
    if (tid == 0) basePos = 0;
    __syncthreads();
    for (int c = 0; c < T_TOK / 256; c++) {
        int t = c * 256 + tid;
        int i0 = g_topi[2*t], i1 = g_topi[2*t+1];
        bool f = (i0 == e) || (i1 == e);
        float w = (i0 == e) ? g_topw[2*t] : g_topw[2*t+1];
        unsigned m = __ballot_sync(0xffffffffu, f);
        int pre = __popc(m & ((1u << lane) - 1));
        if (lane == 0) wcnt[wid] = __popc(m);
        __syncthreads();
        int off = basePos;
        for (int ww = 0; ww < wid; ww++) off += wcnt[ww];
        if (f) { g_tok[e*T_TOK + off + pre] = t; g_wt[e*T_TOK + off + pre] = w; }
        __syncthreads();
        if (tid == 0) { int s = 0; for (int ww = 0; ww < 8; ww++) s += wcnt[ww]; basePos += s; }
        __syncthreads();
    }
    if (tid == 0) g_cnt[e] = basePos;
}

// ---------------- 3) plan: offsets + m-tile map ----------------
__global__ void plan_k() {
    int off = 0, nt = 0;
    for (int e = 0; e < NEXP; e++) {
        g_off[e] = off;
        off += g_cnt[e];
        int ntl = (g_cnt[e] + TILE - 1) >> 7;
        for (int j = 0; j < ntl; j++) { g_tileE[nt] = e; g_tileB[nt] = j << 7; nt++; }
    }
    g_nTiles = nt;
}

// ---------------- 4) fused gate_up GEMM + SwiGLU ----------------
__global__ __launch_bounds__(256, 1) void gateup_k(const float* __restrict__ x,
                                                   const float* __restrict__ wgu) {
    int mt = blockIdx.y;
    if (mt >= g_nTiles) return;
    extern __shared__ float sm[];
    float* As = sm;                    // [2][128][LDA]
    float* Bg = sm + 2 * TILE * LDA;
    float* Bu = sm + 4 * TILE * LDA;
    __shared__ int tokS[TILE];

    int e = g_tileE[mt], base = g_tileB[mt], cnt = g_cnt[e], rowOff = g_off[e];
    int ntB = blockIdx.x * TILE;
    const float* wb = wgu + (size_t)e * GUDIM * HID;
    int useMMA = g_mmaOK;

    int tid = threadIdx.x;
    if (tid < TILE) { int gr = base + tid; tokS[tid] = (gr < cnt) ? g_tok[e*T_TOK + gr] : 0; }
    __syncthreads();

    int lane = tid & 31, wid = tid >> 5;
    int wm = wid >> 2, wn = wid & 3;           // 2 x 4 warps, warp tile 64 x 32
    int gidx = lane >> 2, tgi = lane & 3;

    uint32_t sA = (uint32_t)__cvta_generic_to_shared(As);
    uint32_t sG = (uint32_t)__cvta_generic_to_shared(Bg);
    uint32_t sU = (uint32_t)__cvta_generic_to_shared(Bu);

    auto load = [&](int kt, int b) {
        int k0 = kt * BK;
#pragma unroll
        for (int j = 0; j < 4; j++) {
            int idx = tid + j * 256;
            int r = idx >> 3, kq = (idx & 7) * 4;
            uint32_t doff = (uint32_t)((b * TILE * LDA + r * LDA + kq) * 4);
            { const float* src = x + (size_t)tokS[r] * HID + k0 + kq;
              int sz = (base + r < cnt) ? 16 : 0;
              CP_ASYNC_G(sA + doff, src, sz); }
            { const float* src = wb + (size_t)(ntB + r) * HID + k0 + kq;
              CP_ASYNC_G(sG + doff, src, 16); }
            { const float* src = wb + (size_t)(ntB + r + INTER) * HID + k0 + kq;
              CP_ASYNC_G(sU + doff, src, 16); }
        }
        CP_COMMIT();
    };

    float accg[4][4][4], accu[4][4][4];
#pragma unroll
    for (int a = 0; a < 4; a++)
#pragma unroll
        for (int b = 0; b < 4; b++)
#pragma unroll
            for (int c = 0; c < 4; c++) { accg[a][b][c] = 0.f; accu[a][b][c] = 0.f; }

    const int NK = HID / BK;  // 64
    load(0, 0);
    for (int kt = 0; kt < NK; kt++) {
        int cur = kt & 1;
        if (kt + 1 < NK) { load(kt + 1, (kt + 1) & 1); CP_WAIT(1); }
        else             { CP_WAIT(0); }
        __syncthreads();
        const float* A_ = As + cur * TILE * LDA;
        const float* G_ = Bg + cur * TILE * LDA;
        const float* U_ = Bu + cur * TILE * LDA;
        if (useMMA) {
#pragma unroll
            for (int ks = 0; ks < BK / 8; ks++) {
                int kk = ks * 8;
                uint32_t af[4][4];
#pragma unroll
                for (int im = 0; im < 4; im++) {
                    const float* ap = A_ + (wm*64 + im*16 + gidx) * LDA + kk + tgi;
                    af[im][0] = f2tf32(ap[0]);  af[im][1] = f2tf32(ap[8*LDA]);
                    af[im][2] = f2tf32(ap[4]);  af[im][3] = f2tf32(ap[8*LDA + 4]);
                }
                uint32_t bgf[4][2], buf_[4][2];
#pragma unroll
                for (int in_ = 0; in_ < 4; in_++) {
                    const float* gp = G_ + (wn*32 + in_*8 + gidx) * LDA + kk + tgi;
                    bgf[in_][0] = f2tf32(gp[0]);  bgf[in_][1] = f2tf32(gp[4]);
                    const float* up = U_ + (wn*32 + in_*8 + gidx) * LDA + kk + tgi;
                    buf_[in_][0] = f2tf32(up[0]); buf_[in_][1] = f2tf32(up[4]);
                }
#pragma unroll
                for (int im = 0; im < 4; im++)
#pragma unroll
                    for (int in_ = 0; in_ < 4; in_++) {
                        mma_tf32(accg[im][in_], af[im], bgf[in_]);
                        mma_tf32(accu[im][in_], af[im], buf_[in_]);
                    }
            }
        } else {
            // exact fp32 FMA fallback (same accumulator/fragment mapping)
            for (int k = 0; k < BK; k++) {
                float av[4][2];
#pragma unroll
                for (int im = 0; im < 4; im++) {
                    const float* ap = A_ + (wm*64 + im*16 + gidx) * LDA + k;
                    av[im][0] = ap[0]; av[im][1] = ap[8*LDA];
                }
#pragma unroll
                for (int in_ = 0; in_ < 4; in_++) {
                    int nr = (wn*32 + in_*8 + tgi*2);
                    float g0 = G_[nr*LDA + k], g1 = G_[(nr+1)*LDA + k];
                    float u0 = U_[nr*LDA + k], u1 = U_[(nr+1)*LDA + k];
#pragma unroll
                    for (int im = 0; im < 4; im++) {
                        accg[im][in_][0] += av[im][0]*g0; accg[im][in_][1] += av[im][0]*g1;
                        accg[im][in_][2] += av[im][1]*g0; accg[im][in_][3] += av[im][1]*g1;
                        accu[im][in_][0] += av[im][0]*u0; accu[im][in_][1] += av[im][0]*u1;
                        accu[im][in_][2] += av[im][1]*u0; accu[im][in_][3] += av[im][1]*u1;
                    }
                }
            }
        }
        __syncthreads();
    }

    // epilogue: silu(g)*u -> inter scratch
#pragma unroll
    for (int im = 0; im < 4; im++) {
        int r0 = wm*64 + im*16 + gidx;
#pragma unroll
        for (int in_ = 0; in_ < 4; in_++) {
            int cb = wn*32 + in_*8 + tgi*2;
            if (base + r0 < cnt) {
                float gg0 = accg[im][in_][0], gg1 = accg[im][in_][1];
                float2 v;
                v.x = gg0 / (1.f + __expf(-gg0)) * accu[im][in_][0];
                v.y = gg1 / (1.f + __expf(-gg1)) * accu[im][in_][1];
                *(float2*)(g_inter + (size_t)(rowOff + base + r0) * INTER + ntB + cb) = v;
            }
            if (base + r0 + 8 < cnt) {
                float gg2 = accg[im][in_][2], gg3 = accg[im][in_][3];
                float2 v;
                v.x = gg2 / (1.f + __expf(-gg2)) * accu[im][in_][2];
                v.y = gg3 / (1.f + __expf(-gg3)) * accu[im][in_][3];
                *(float2*)(g_inter + (size_t)(rowOff + base + r0 + 8) * INTER + ntB + cb) = v;
            }
        }
    }
}

// ---------------- 5) down GEMM * weight, scatter-add ----------------
__global__ __launch_bounds__(256, 1) void down_k(const float* __restrict__ wd,
                                                 float* __restrict__ out) {
    int mt = blockIdx.y;
    if (mt >= g_nTiles) return;
    extern __shared__ float sm[];
    float* As = sm;
    float* Bd = sm + 2 * TILE * LDA;

    int e = g_tileE[mt], base = g_tileB[mt], cnt = g_cnt[e], rowOff = g_off[e];
    int ntB = blockIdx.x * TILE;
    const float* wb = wd + (size_t)e * HID * INTER;
    int useMMA = g_mmaOK;

    int tid = threadIdx.x;
    int lane = tid & 31, wid = tid >> 5;
    int wm = wid >> 2, wn = wid & 3;
    int gidx = lane >> 2, tgi = lane & 3;

    uint32_t sA = (uint32_t)__cvta_generic_to_shared(As);
    uint32_t sB = (uint32_t)__cvta_generic_to_shared(Bd);

    auto load = [&](int kt, int b) {
        int k0 = kt * BK;
#pragma unroll
        for (int j = 0; j < 4; j++) {
            int idx = tid + j * 256;
            int r = idx >> 3, kq = (idx & 7) * 4;
            uint32_t doff = (uint32_t)((b * TILE * LDA + r * LDA + kq) * 4);
            { const float* src = g_inter + (size_t)(rowOff + base + r) * INTER + k0 + kq;
              int sz = (base + r < cnt) ? 16 : 0;
              CP_ASYNC_G(sA + doff, src, sz); }
            { const float* src = wb + (size_t)(ntB + r) * INTER + k0 + kq;
              CP_ASYNC_G(sB + doff, src, 16); }
        }
        CP_COMMIT();
    };

    float acc[4][4][4];
#pragma unroll
    for (int a = 0; a < 4; a++)
#pragma unroll
        for (int b = 0; b < 4; b++)
#pragma unroll
            for (int c = 0; c < 4; c++) acc[a][b][c] = 0.f;

    const int NK = INTER / BK;  // 88
    load(0, 0);
    for (int kt = 0; kt < NK; kt++) {
        int cur = kt & 1;
        if (kt + 1 < NK) { load(kt + 1, (kt + 1) & 1); CP_WAIT(1); }
        else             { CP_WAIT(0); }
        __syncthreads();
        const float* A_ = As + cur * TILE * LDA;
        const float* B_ = Bd + cur * TILE * LDA;
        if (useMMA) {
#pragma unroll
            for (int ks = 0; ks < BK / 8; ks++) {
                int kk = ks * 8;
                uint32_t af[4][4];
#pragma unroll
                for (int im = 0; im < 4; im++) {
                    const float* ap = A_ + (wm*64 + im*16 + gidx) * LDA + kk + tgi;
                    af[im][0] = f2tf32(ap[0]);  af[im][1] = f2tf32(ap[8*LDA]);
                    af[im][2] = f2tf32(ap[4]);  af[im][3] = f2tf32(ap[8*LDA + 4]);
                }
                uint32_t bf[4][2];
#pragma unroll
                for (int in_ = 0; in_ < 4; in_++) {
                    const float* bp = B_ + (wn*32 + in_*8 + gidx) * LDA + kk + tgi;
                    bf[in_][0] = f2tf32(bp[0]); bf[in_][1] = f2tf32(bp[4]);
                }
#pragma unroll
                for (int im = 0; im < 4; im++)
#pragma unroll
                    for (int in_ = 0; in_ < 4; in_++)
                        mma_tf32(acc[im][in_], af[im], bf[in_]);
            }
        } else {
            for (int k = 0; k < BK; k++) {
                float av[4][2];
#pragma unroll
                for (int im = 0; im < 4; im++) {
                    const float* ap = A_ + (wm*64 + im*16 + gidx) * LDA + k;
                    av[im][0] = ap[0]; av[im][1] = ap[8*LDA];
                }
#pragma unroll
                for (int in_ = 0; in_ < 4; in_++) {
                    int nr = (wn*32 + in_*8 + tgi*2);
                    float b0 = B_[nr*LDA + k], b1 = B_[(nr+1)*LDA + k];
#pragma unroll
                    for (int im = 0; im < 4; im++) {
                        acc[im][in_][0] += av[im][0]*b0; acc[im][in_][1] += av[im][0]*b1;
                        acc[im][in_][2] += av[im][1]*b0; acc[im][in_][3] += av[im][1]*b1;
                    }
                }
            }
        }
        __syncthreads();
    }

    // epilogue: scale by routing weight, scatter atomicAdd
    // FIX (R3): output column must include the n-tile base offset ntB.
#pragma unroll
    for (int im = 0; im < 4; im++) {
        int r0 = wm*64 + im*16 + gidx;
#pragma unroll
        for (int in_ = 0; in_ < 4; in_++) {
            int cb = ntB + wn*32 + in_*8 + tgi*2;
            if (base + r0 < cnt) {
                int tok = g_tok[e*T_TOK + base + r0];
                float w = g_wt[e*T_TOK + base + r0];
                float* o = out + (size_t)tok * HID + cb;
                atomicAdd(o,     acc[im][in_][0] * w);
                atomicAdd(o + 1, acc[im][in_][1] * w);
            }
            if (base + r0 + 8 < cnt) {
                int tok = g_tok[e*T_TOK + base + r0 + 8];
                float w = g_wt[e*T_TOK + base + r0 + 8];
                float* o = out + (size_t)tok * HID + cb;
                atomicAdd(o,     acc[im][in_][2] * w);
                atomicAdd(o + 1, acc[im][in_][3] * w);
            }
        }
    }
}

// ---------------- launch: bind inputs by SIZE, not position ----------------
extern "C" void kernel_launch(void* const* d_in, const int* in_sizes, int n_in,
                              void* d_out, int out_size) {
    // positional defaults (dict order) then override by unique element counts
    const float* x   = (const float*)d_in[0];
    const float* gw  = (const float*)d_in[1];
    const float* b1  = (const float*)d_in[2];
    const float* b2  = (const float*)d_in[3];
    const float* wgu = (const float*)d_in[4];
    const float* wd  = (const float*)d_in[5];
    int nb = 0;
    for (int i = 0; i < n_in; i++) {
        long s = (long)in_sizes[i];
        const float* p = (const float*)d_in[i];
        if      (s == (long)T_TOK * HID)         x   = p;
        else if (s == (long)NEXP * HID)          gw  = p;
        else if (s == (long)NEXP * GUDIM * HID)  wgu = p;
        else if (s == (long)NEXP * HID * INTER)  wd  = p;
        else if (s == (long)NEXP)                { if (nb == 0) b1 = p; else b2 = p; nb++; }
    }
    float* out = (float*)d_out;

    cudaFuncSetAttribute(gateup_k, cudaFuncAttributeMaxDynamicSharedMemorySize, 6 * TILE * LDA * 4);
    cudaFuncSetAttribute(down_k,   cudaFuncAttributeMaxDynamicSharedMemorySize, 4 * TILE * LDA * 4);

    cudaMemsetAsync(d_out, 0, (size_t)T_TOK * HID * sizeof(float));
    mmatest_k<<<1, 32>>>();
    router_k<<<T_TOK / 8, 256>>>(x, gw, b1, b2);
    lists_k<<<NEXP, 256>>>();
    plan_k<<<1, 1>>>();
    gateup_k<<<dim3(INTER / TILE, MAX_MT), 256, 6 * TILE * LDA * 4>>>(x, wgu);
    down_k<<<dim3(HID / TILE, MAX_MT), 256, 4 * TILE * LDA * 4>>>(wd, out);
}

// round 6
// speedup vs baseline: 1.5690x; 1.5690x over previous
#include <cuda_runtime.h>
#include <cstdint>

#define T_TOK 8192
#define HID   2048
#define NEXP  8
#define INTER 2816
#define GUDIM (2*INTER)
#define MAX_MT 136
#define TILE 128
#define BK   32
#define LDA  36   // padded smem row stride (floats)

// ---------------- scratch (device globals: no allocations allowed) ----------------
__device__ int    g_topi[T_TOK*2];
__device__ float  g_topw[T_TOK*2];
__device__ int    g_tok [NEXP*T_TOK];
__device__ float  g_wt  [NEXP*T_TOK];
__device__ int    g_cnt [NEXP];
__device__ int    g_off [NEXP];
__device__ int    g_tileE[MAX_MT+8];
__device__ int    g_tileB[MAX_MT+8];
__device__ int    g_nTiles;
__device__ int    g_mmaOK;
__device__ __align__(16) float g_inter[(size_t)(16384+128)*INTER];   // ~186 MB

// ---------------- helpers ----------------
__device__ __forceinline__ uint32_t f2tf32(float f) {
    uint32_t u;
    asm volatile("cvt.rna.tf32.f32 %0, %1;\n" : "=r"(u) : "f"(f));
    return u;
}

__device__ __forceinline__ void mma_tf32(float* d, const uint32_t* a, const uint32_t* b) {
    asm volatile(
        "mma.sync.aligned.m16n8k8.row.col.f32.tf32.tf32.f32 "
        "{%0,%1,%2,%3}, {%4,%5,%6,%7}, {%8,%9}, {%0,%1,%2,%3};\n"
        : "+f"(d[0]), "+f"(d[1]), "+f"(d[2]), "+f"(d[3])
        : "r"(a[0]), "r"(a[1]), "r"(a[2]), "r"(a[3]), "r"(b[0]), "r"(b[1]));
}

#define CP_ASYNC_G(dst, src, sz) \
    asm volatile("cp.async.cg.shared.global [%0], [%1], 16, %2;\n" :: "r"(dst), "l"(src), "r"(sz))
#define CP_COMMIT() asm volatile("cp.async.commit_group;\n")
#define CP_WAIT(n)  asm volatile("cp.async.wait_group %0;\n" :: "n"(n))

// ---------------- 0) mma self-test: validates instruction + fragment layout ----------------
__global__ void mmatest_k() {
    __shared__ float As[16][8];  // [m][k]
    __shared__ float Bs[8][8];   // [n][k]
    int lane = threadIdx.x & 31;
    if (lane < 16)
        for (int k = 0; k < 8; k++) As[lane][k] = (float)((lane * 3 + k * 5) % 7 - 3);
    if (lane < 8)
        for (int k = 0; k < 8; k++) Bs[lane][k] = (float)((lane * 5 + k * 3) % 5 - 2);
    __syncwarp();
    int g = lane >> 2, t = lane & 3;
    uint32_t a[4], b[2];
    a[0] = f2tf32(As[g][t]);     a[1] = f2tf32(As[g + 8][t]);
    a[2] = f2tf32(As[g][t + 4]); a[3] = f2tf32(As[g + 8][t + 4]);
    b[0] = f2tf32(Bs[g][t]);     b[1] = f2tf32(Bs[g][t + 4]);
    float d[4] = {0.f, 0.f, 0.f, 0.f};
    mma_tf32(d, a, b);
    bool ok = true;
    int mr[2] = {g, g + 8}, nc[2] = {2 * t, 2 * t + 1};
    for (int i = 0; i < 2; i++)
        for (int j = 0; j < 2; j++) {
            float ref = 0.f;
            for (int k = 0; k < 8; k++) ref += As[mr[i]][k] * Bs[nc[j]][k];
            if (d[i * 2 + j] != ref) ok = false;   // integer data: exact
        }
    unsigned m = __ballot_sync(0xffffffffu, ok);
    if (lane == 0) g_mmaOK = (m == 0xffffffffu) ? 1 : 0;
}

// ---------------- 1) router (fp64 accum; biases applied post-softmax, exact since gate_b==0) ----
__global__ void router_k(const float* __restrict__ x, const float* __restrict__ gw,
                         const float* __restrict__ b1, const float* __restrict__ b2) {
    int lane = threadIdx.x & 31, wid = threadIdx.x >> 5;
    int t = blockIdx.x * 8 + wid;
    const float* xr = x + (size_t)t * HID;
    double acc[NEXP];
#pragma unroll
    for (int e = 0; e < NEXP; e++) acc[e] = 0.0;
    for (int i = lane; i < HID; i += 32) {
        float xv = xr[i];
#pragma unroll
        for (int e = 0; e < NEXP; e++)
            acc[e] += (double)xv * (double)gw[e * HID + i];
    }
#pragma unroll
    for (int e = 0; e < NEXP; e++) {
        double v = acc[e];
        for (int o = 16; o; o >>= 1) v += __shfl_down_sync(0xffffffffu, v, o);
        acc[e] = v;
    }
    if (lane == 0) {
        float l[NEXP], m = -1e30f;
#pragma unroll
        for (int e = 0; e < NEXP; e++) { l[e] = (float)acc[e]; m = fmaxf(m, l[e]); }
        float s = 0.f, p[NEXP];
#pragma unroll
        for (int e = 0; e < NEXP; e++) { p[e] = expf(l[e] - m); s += p[e]; }
        float r[NEXP];
#pragma unroll
        for (int e = 0; e < NEXP; e++) r[e] = p[e] / s + b1[e] + b2[e];
        int c1 = 0;
#pragma unroll
        for (int e = 1; e < NEXP; e++) if (r[e] > r[c1]) c1 = e;
        int c2 = (c1 == 0) ? 1 : 0;
#pragma unroll
        for (int e = 0; e < NEXP; e++) if (e != c1 && r[e] > r[c2]) c2 = e;
        g_topi[2*t] = c1; g_topi[2*t+1] = c2;
        g_topw[2*t] = r[c1]; g_topw[2*t+1] = r[c2];
    }
}

// ---------------- 2) deterministic per-expert token lists ----------------
__global__ void lists_k() {
    int e = blockIdx.x, tid = threadIdx.x, lane = tid & 31, wid = tid >> 5;
    __shared__ int wcnt[8];
    __shared__ int basePos;
    if (tid == 0) basePos = 0;
    __syncthreads();
    for (int c = 0; c < T_TOK / 256; c++) {
        int t = c * 256 + tid;
        int i0 = g_topi[2*t], i1 = g_topi[2*t+1];
        bool f = (i0 == e) || (i1 == e);
        float w = (i0 == e) ? g_topw[2*t] : g_topw[2*t+1];
        unsigned m = __ballot_sync(0xffffffffu, f);
        int pre = __popc(m & ((1u << lane) - 1));
        if (lane == 0) wcnt[wid] = __popc(m);
        __syncthreads();
        int off = basePos;
        for (int ww = 0; ww < wid; ww++) off += wcnt[ww];
        if (f) { g_tok[e*T_TOK + off + pre] = t; g_wt[e*T_TOK + off + pre] = w; }
        __syncthreads();
        if (tid == 0) { int s = 0; for (int ww = 0; ww < 8; ww++) s += wcnt[ww]; basePos += s; }
        __syncthreads();
    }
    if (tid == 0) g_cnt[e] = basePos;
}

// ---------------- 3) plan: offsets + m-tile map ----------------
__global__ void plan_k() {
    int off = 0, nt = 0;
    for (int e = 0; e < NEXP; e++) {
        g_off[e] = off;
        off += g_cnt[e];
        int ntl = (g_cnt[e] + TILE - 1) >> 7;
        for (int j = 0; j < ntl; j++) { g_tileE[nt] = e; g_tileB[nt] = j << 7; nt++; }
    }
    g_nTiles = nt;
}

// ---------------- 4) fused gate_up GEMM + SwiGLU ----------------
__global__ __launch_bounds__(256, 1) void gateup_k(const float* __restrict__ x,
                                                   const float* __restrict__ wgu) {
    int mt = blockIdx.y;
    if (mt >= g_nTiles) return;
    extern __shared__ float sm[];
    float* As = sm;                    // [2][128][LDA]
    float* Bg = sm + 2 * TILE * LDA;
    float* Bu = sm + 4 * TILE * LDA;
    __shared__ int tokS[TILE];

    int e = g_tileE[mt], base = g_tileB[mt], cnt = g_cnt[e], rowOff = g_off[e];
    int ntB = blockIdx.x * TILE;
    const float* wb = wgu + (size_t)e * GUDIM * HID;
    int useMMA = g_mmaOK;

    int tid = threadIdx.x;
    if (tid < TILE) { int gr = base + tid; tokS[tid] = (gr < cnt) ? g_tok[e*T_TOK + gr] : 0; }
    __syncthreads();

    int lane = tid & 31, wid = tid >> 5;
    int wm = wid >> 2, wn = wid & 3;           // 2 x 4 warps, warp tile 64 x 32
    int gidx = lane >> 2, tgi = lane & 3;

    uint32_t sA = (uint32_t)__cvta_generic_to_shared(As);
    uint32_t sG = (uint32_t)__cvta_generic_to_shared(Bg);
    uint32_t sU = (uint32_t)__cvta_generic_to_shared(Bu);

    auto load = [&](int kt, int b) {
        int k0 = kt * BK;
#pragma unroll
        for (int j = 0; j < 4; j++) {
            int idx = tid + j * 256;
            int r = idx >> 3, kq = (idx & 7) * 4;
            uint32_t doff = (uint32_t)((b * TILE * LDA + r * LDA + kq) * 4);
            { const float* src = x + (size_t)tokS[r] * HID + k0 + kq;
              int sz = (base + r < cnt) ? 16 : 0;
              CP_ASYNC_G(sA + doff, src, sz); }
            { const float* src = wb + (size_t)(ntB + r) * HID + k0 + kq;
              CP_ASYNC_G(sG + doff, src, 16); }
            { const float* src = wb + (size_t)(ntB + r + INTER) * HID + k0 + kq;
              CP_ASYNC_G(sU + doff, src, 16); }
        }
        CP_COMMIT();
    };

    float accg[4][4][4], accu[4][4][4];
#pragma unroll
    for (int a = 0; a < 4; a++)
#pragma unroll
        for (int b = 0; b < 4; b++)
#pragma unroll
            for (int c = 0; c < 4; c++) { accg[a][b][c] = 0.f; accu[a][b][c] = 0.f; }

    const int NK = HID / BK;  // 64
    load(0, 0);
    for (int kt = 0; kt < NK; kt++) {
        int cur = kt & 1;
        if (kt + 1 < NK) { load(kt + 1, (kt + 1) & 1); CP_WAIT(1); }
        else             { CP_WAIT(0); }
        __syncthreads();
        const float* A_ = As + cur * TILE * LDA;
        const float* G_ = Bg + cur * TILE * LDA;
        const float* U_ = Bu + cur * TILE * LDA;
        if (useMMA) {
#pragma unroll
            for (int ks = 0; ks < BK / 8; ks++) {
                int kk = ks * 8;
                uint32_t af[4][4];
#pragma unroll
                for (int im = 0; im < 4; im++) {
                    const float* ap = A_ + (wm*64 + im*16 + gidx) * LDA + kk + tgi;
                    af[im][0] = f2tf32(ap[0]);  af[im][1] = f2tf32(ap[8*LDA]);
                    af[im][2] = f2tf32(ap[4]);  af[im][3] = f2tf32(ap[8*LDA + 4]);
                }
                uint32_t bgf[4][2], buf_[4][2];
#pragma unroll
                for (int in_ = 0; in_ < 4; in_++) {
                    const float* gp = G_ + (wn*32 + in_*8 + gidx) * LDA + kk + tgi;
                    bgf[in_][0] = f2tf32(gp[0]);  bgf[in_][1] = f2tf32(gp[4]);
                    const float* up = U_ + (wn*32 + in_*8 + gidx) * LDA + kk + tgi;
                    buf_[in_][0] = f2tf32(up[0]); buf_[in_][1] = f2tf32(up[4]);
                }
#pragma unroll
                for (int im = 0; im < 4; im++)
#pragma unroll
                    for (int in_ = 0; in_ < 4; in_++) {
                        mma_tf32(accg[im][in_], af[im], bgf[in_]);
                        mma_tf32(accu[im][in_], af[im], buf_[in_]);
                    }
            }
        } else {
            // exact fp32 FMA fallback (same accumulator/fragment mapping)
            for (int k = 0; k < BK; k++) {
                float av[4][2];
#pragma unroll
                for (int im = 0; im < 4; im++) {
                    const float* ap = A_ + (wm*64 + im*16 + gidx) * LDA + k;
                    av[im][0] = ap[0]; av[im][1] = ap[8*LDA];
                }
#pragma unroll
                for (int in_ = 0; in_ < 4; in_++) {
                    int nr = (wn*32 + in_*8 + tgi*2);
                    float g0 = G_[nr*LDA + k], g1 = G_[(nr+1)*LDA + k];
                    float u0 = U_[nr*LDA + k], u1 = U_[(nr+1)*LDA + k];
#pragma unroll
                    for (int im = 0; im < 4; im++) {
                        accg[im][in_][0] += av[im][0]*g0; accg[im][in_][1] += av[im][0]*g1;
                        accg[im][in_][2] += av[im][1]*g0; accg[im][in_][3] += av[im][1]*g1;
                        accu[im][in_][0] += av[im][0]*u0; accu[im][in_][1] += av[im][0]*u1;
                        accu[im][in_][2] += av[im][1]*u0; accu[im][in_][3] += av[im][1]*u1;
                    }
                }
            }
        }
        __syncthreads();
    }

    // epilogue: silu(g)*u -> inter scratch
#pragma unroll
    for (int im = 0; im < 4; im++) {
        int r0 = wm*64 + im*16 + gidx;
#pragma unroll
        for (int in_ = 0; in_ < 4; in_++) {
            int cb = wn*32 + in_*8 + tgi*2;
            if (base + r0 < cnt) {
                float gg0 = accg[im][in_][0], gg1 = accg[im][in_][1];
                float2 v;
                v.x = gg0 / (1.f + __expf(-gg0)) * accu[im][in_][0];
                v.y = gg1 / (1.f + __expf(-gg1)) * accu[im][in_][1];
                *(float2*)(g_inter + (size_t)(rowOff + base + r0) * INTER + ntB + cb) = v;
            }
            if (base + r0 + 8 < cnt) {
                float gg2 = accg[im][in_][2], gg3 = accg[im][in_][3];
                float2 v;
                v.x = gg2 / (1.f + __expf(-gg2)) * accu[im][in_][2];
                v.y = gg3 / (1.f + __expf(-gg3)) * accu[im][in_][3];
                *(float2*)(g_inter + (size_t)(rowOff + base + r0 + 8) * INTER + ntB + cb) = v;
            }
        }
    }
}

// ---------------- 5) down GEMM * weight, scatter-add ----------------
__global__ __launch_bounds__(256, 1) void down_k(const float* __restrict__ wd,
                                                 float* __restrict__ out) {
    int mt = blockIdx.y;
    if (mt >= g_nTiles) return;
    extern __shared__ float sm[];
    float* As = sm;
    float* Bd = sm + 2 * TILE * LDA;

    int e = g_tileE[mt], base = g_tileB[mt], cnt = g_cnt[e], rowOff = g_off[e];
    int ntB = blockIdx.x * TILE;
    const float* wb = wd + (size_t)e * HID * INTER;
    int useMMA = g_mmaOK;

    int tid = threadIdx.x;
    int lane = tid & 31, wid = tid >> 5;
    int wm = wid >> 2, wn = wid & 3;
    int gidx = lane >> 2, tgi = lane & 3;

    uint32_t sA = (uint32_t)__cvta_generic_to_shared(As);
    uint32_t sB = (uint32_t)__cvta_generic_to_shared(Bd);

    auto load = [&](int kt, int b) {
        int k0 = kt * BK;
#pragma unroll
        for (int j = 0; j < 4; j++) {
            int idx = tid + j * 256;
            int r = idx >> 3, kq = (idx & 7) * 4;
            uint32_t doff = (uint32_t)((b * TILE * LDA + r * LDA + kq) * 4);
            { const float* src = g_inter + (size_t)(rowOff + base + r) * INTER + k0 + kq;
              int sz = (base + r < cnt) ? 16 : 0;
              CP_ASYNC_G(sA + doff, src, sz); }
            { const float* src = wb + (size_t)(ntB + r) * INTER + k0 + kq;
              CP_ASYNC_G(sB + doff, src, 16); }
        }
        CP_COMMIT();
    };

    float acc[4][4][4];
#pragma unroll
    for (int a = 0; a < 4; a++)
#pragma unroll
        for (int b = 0; b < 4; b++)
#pragma unroll
            for (int c = 0; c < 4; c++) acc[a][b][c] = 0.f;

    const int NK = INTER / BK;  // 88
    load(0, 0);
    for (int kt = 0; kt < NK; kt++) {
        int cur = kt & 1;
        if (kt + 1 < NK) { load(kt + 1, (kt + 1) & 1); CP_WAIT(1); }
        else             { CP_WAIT(0); }
        __syncthreads();
        const float* A_ = As + cur * TILE * LDA;
        const float* B_ = Bd + cur * TILE * LDA;
        if (useMMA) {
#pragma unroll
            for (int ks = 0; ks < BK / 8; ks++) {
                int kk = ks * 8;
                uint32_t af[4][4];
#pragma unroll
                for (int im = 0; im < 4; im++) {
                    const float* ap = A_ + (wm*64 + im*16 + gidx) * LDA + kk + tgi;
                    af[im][0] = f2tf32(ap[0]);  af[im][1] = f2tf32(ap[8*LDA]);
                    af[im][2] = f2tf32(ap[4]);  af[im][3] = f2tf32(ap[8*LDA + 4]);
                }
                uint32_t bf[4][2];
#pragma unroll
                for (int in_ = 0; in_ < 4; in_++) {
                    const float* bp = B_ + (wn*32 + in_*8 + gidx) * LDA + kk + tgi;
                    bf[in_][0] = f2tf32(bp[0]); bf[in_][1] = f2tf32(bp[4]);
                }
#pragma unroll
                for (int im = 0; im < 4; im++)
#pragma unroll
                    for (int in_ = 0; in_ < 4; in_++)
                        mma_tf32(acc[im][in_], af[im], bf[in_]);
            }
        } else {
            for (int k = 0; k < BK; k++) {
                float av[4][2];
#pragma unroll
                for (int im = 0; im < 4; im++) {
                    const float* ap = A_ + (wm*64 + im*16 + gidx) * LDA + k;
                    av[im][0] = ap[0]; av[im][1] = ap[8*LDA];
                }
#pragma unroll
                for (int in_ = 0; in_ < 4; in_++) {
                    int nr = (wn*32 + in_*8 + tgi*2);
                    float b0 = B_[nr*LDA + k], b1 = B_[(nr+1)*LDA + k];
#pragma unroll
                    for (int im = 0; im < 4; im++) {
                        acc[im][in_][0] += av[im][0]*b0; acc[im][in_][1] += av[im][0]*b1;
                        acc[im][in_][2] += av[im][1]*b0; acc[im][in_][3] += av[im][1]*b1;
                    }
                }
            }
        }
        __syncthreads();
    }

    // epilogue: scale by routing weight, scatter atomicAdd
    // FIX (R3): output column must include the n-tile base offset ntB.
#pragma unroll
    for (int im = 0; im < 4; im++) {
        int r0 = wm*64 + im*16 + gidx;
#pragma unroll
        for (int in_ = 0; in_ < 4; in_++) {
            int cb = ntB + wn*32 + in_*8 + tgi*2;
            if (base + r0 < cnt) {
                int tok = g_tok[e*T_TOK + base + r0];
                float w = g_wt[e*T_TOK + base + r0];
                float* o = out + (size_t)tok * HID + cb;
                atomicAdd(o,     acc[im][in_][0] * w);
                atomicAdd(o + 1, acc[im][in_][1] * w);
            }
            if (base + r0 + 8 < cnt) {
                int tok = g_tok[e*T_TOK + base + r0 + 8];
                float w = g_wt[e*T_TOK + base + r0 + 8];
                float* o = out + (size_t)tok * HID + cb;
                atomicAdd(o,     acc[im][in_][2] * w);
                atomicAdd(o + 1, acc[im][in_][3] * w);
            }
        }
    }
}

// ---------------- launch: bind inputs by SIZE, not position ----------------
extern "C" void kernel_launch(void* const* d_in, const int* in_sizes, int n_in,
                              void* d_out, int out_size) {
    // positional defaults (dict order) then override by unique element counts
    const float* x   = (const float*)d_in[0];
    const float* gw  = (const float*)d_in[1];
    const float* b1  = (const float*)d_in[2];
    const float* b2  = (const float*)d_in[3];
    const float* wgu = (const float*)d_in[4];
    const float* wd  = (const float*)d_in[5];
    int nb = 0;
    for (int i = 0; i < n_in; i++) {
        long s = (long)in_sizes[i];
        const float* p = (const float*)d_in[i];
        if      (s == (long)T_TOK * HID)         x   = p;
        else if (s == (long)NEXP * HID)          gw  = p;
        else if (s == (long)NEXP * GUDIM * HID)  wgu = p;
        else if (s == (long)NEXP * HID * INTER)  wd  = p;
        else if (s == (long)NEXP)                { if (nb == 0) b1 = p; else b2 = p; nb++; }
    }
    float* out = (float*)d_out;

    cudaFuncSetAttribute(gateup_k, cudaFuncAttributeMaxDynamicSharedMemorySize, 6 * TILE * LDA * 4);
    cudaFuncSetAttribute(down_k,   cudaFuncAttributeMaxDynamicSharedMemorySize, 4 * TILE * LDA * 4);

    cudaMemsetAsync(d_out, 0, (size_t)T_TOK * HID * sizeof(float));
    mmatest_k<<<1, 32>>>();
    router_k<<<T_TOK / 8, 256>>>(x, gw, b1, b2);
    lists_k<<<NEXP, 256>>>();
    plan_k<<<1, 1>>>();
    gateup_k<<<dim3(INTER / TILE, MAX_MT), 256, 6 * TILE * LDA * 4>>>(x, wgu);
    down_k<<<dim3(HID / TILE, MAX_MT), 256, 4 * TILE * LDA * 4>>>(wd, out);
}